// round 1
// baseline (speedup 1.0000x reference)
#include <cuda_runtime.h>
#include <math.h>
#include <stdint.h>

// ---------------------------------------------------------------------------
// Problem constants
// ---------------------------------------------------------------------------
#define BDIM   2
#define SEQ    1024
#define DMODEL 768
#define NHEADS 12
#define HDIM   64
#define DMLP   3072
#define TTOK   (BDIM * SEQ)          // 2048 tokens
#define QK_SCALE 0.125f              // HDIM^-0.5

// ---------------------------------------------------------------------------
// Scratch (static __device__ globals: allocation-guard safe)
// ---------------------------------------------------------------------------
static __device__ __align__(16) float g_h[TTOK * DMODEL];              //  6 MB  (LN out, reused)
static __device__ __align__(16) float g_qkv[TTOK * 3 * DMODEL];        // 18 MB
static __device__ __align__(16) float g_qk[(size_t)BDIM * NHEADS * SEQ * SEQ]; // 100 MB raw logits
static __device__ __align__(16) float g_attnout[TTOK * DMODEL];        //  6 MB
static __device__ __align__(16) float g_x1[TTOK * DMODEL];             //  6 MB
static __device__ __align__(16) float g_mlp[(size_t)TTOK * DMLP];      // 24 MB

// ---------------------------------------------------------------------------
// LayerNorm: one block (256 thr) per token row of length DMODEL
// ---------------------------------------------------------------------------
__global__ void ln_kernel(const float* __restrict__ x, const float* __restrict__ g,
                          const float* __restrict__ b, float* __restrict__ out) {
    int row = blockIdx.x;
    const float* xr = x + (size_t)row * DMODEL;
    float* orow = out + (size_t)row * DMODEL;
    __shared__ float red[256];
    int tid = threadIdx.x;

    float s = 0.f;
    for (int i = tid; i < DMODEL; i += 256) s += xr[i];
    red[tid] = s; __syncthreads();
    for (int k = 128; k > 0; k >>= 1) { if (tid < k) red[tid] += red[tid + k]; __syncthreads(); }
    float mu = red[0] * (1.0f / DMODEL);
    __syncthreads();

    float v = 0.f;
    for (int i = tid; i < DMODEL; i += 256) { float d = xr[i] - mu; v += d * d; }
    red[tid] = v; __syncthreads();
    for (int k = 128; k > 0; k >>= 1) { if (tid < k) red[tid] += red[tid + k]; __syncthreads(); }
    float rstd = rsqrtf(red[0] * (1.0f / DMODEL) + 1e-5f);

    for (int i = tid; i < DMODEL; i += 256)
        orow[i] = (xr[i] - mu) * rstd * g[i] + b[i];
}

// ---------------------------------------------------------------------------
// GELU (jax.nn.gelu default = tanh approximation)
// ---------------------------------------------------------------------------
__device__ __forceinline__ float gelu_tanh(float x) {
    float x3 = x * x * x;
    float t = tanhf(0.7978845608028654f * (x + 0.044715f * x3));
    return 0.5f * x * (1.0f + t);
}

// ---------------------------------------------------------------------------
// Generic NT SGEMM: C[M,N] = A[M,K] @ W[N,K]^T + bias (+res) (+gelu)
// Tiles 128x128x16, 256 threads, 8x8 per thread. M,N multiples of 128,
// K multiple of 16 (all true for this problem).
// ---------------------------------------------------------------------------
template <int ACT, bool RES>
__global__ __launch_bounds__(256)
void gemm_nt(const float* __restrict__ A, const float* __restrict__ W,
             const float* __restrict__ bias, const float* __restrict__ res,
             float* __restrict__ C, int M, int N, int K) {
    constexpr int BM = 128, BN = 128, BK = 16;
    __shared__ float As[BK][BM + 4];
    __shared__ float Ws[BK][BN + 4];
    int tid = threadIdx.x;
    int tx = tid % 16, ty = tid / 16;
    const float* Ab = A + (size_t)(blockIdx.y * BM) * K;
    const float* Wb = W + (size_t)(blockIdx.x * BN) * K;

    float acc[8][8];
#pragma unroll
    for (int i = 0; i < 8; i++)
#pragma unroll
        for (int j = 0; j < 8; j++) acc[i][j] = 0.f;

    for (int k0 = 0; k0 < K; k0 += BK) {
#pragma unroll
        for (int e = tid; e < 512; e += 256) {
            int row = e >> 2, c4 = e & 3;
            float4 a = *(const float4*)(Ab + (size_t)row * K + k0 + c4 * 4);
            As[c4 * 4 + 0][row] = a.x; As[c4 * 4 + 1][row] = a.y;
            As[c4 * 4 + 2][row] = a.z; As[c4 * 4 + 3][row] = a.w;
            float4 w = *(const float4*)(Wb + (size_t)row * K + k0 + c4 * 4);
            Ws[c4 * 4 + 0][row] = w.x; Ws[c4 * 4 + 1][row] = w.y;
            Ws[c4 * 4 + 2][row] = w.z; Ws[c4 * 4 + 3][row] = w.w;
        }
        __syncthreads();
#pragma unroll
        for (int kk = 0; kk < BK; kk++) {
            float a[8], w[8];
#pragma unroll
            for (int i = 0; i < 8; i++) a[i] = As[kk][ty * 8 + i];
#pragma unroll
            for (int j = 0; j < 8; j++) w[j] = Ws[kk][tx * 8 + j];
#pragma unroll
            for (int i = 0; i < 8; i++)
#pragma unroll
                for (int j = 0; j < 8; j++) acc[i][j] = fmaf(a[i], w[j], acc[i][j]);
        }
        __syncthreads();
    }

#pragma unroll
    for (int i = 0; i < 8; i++) {
        int row = blockIdx.y * BM + ty * 8 + i;
#pragma unroll
        for (int j = 0; j < 8; j++) {
            int col = blockIdx.x * BN + tx * 8 + j;
            float v = acc[i][j] + bias[col];
            if (ACT == 1) v = gelu_tanh(v);
            if (RES) v += res[(size_t)row * N + col];
            C[(size_t)row * N + col] = v;
        }
    }
}

// ---------------------------------------------------------------------------
// Batched QK^T: per (b,h): qk[n,m] = sum_d q[n,d]*k[m,d]  (raw, unscaled)
// q/k strided views into g_qkv (row stride 3*DMODEL).
// ---------------------------------------------------------------------------
__global__ __launch_bounds__(256)
void qk_kernel() {
    constexpr int BM = 128, BN = 128, BK = 16;
    constexpr int LDA = 3 * DMODEL;
    __shared__ float Qs[BK][BM + 4];
    __shared__ float Ks[BK][BN + 4];
    int bh = blockIdx.z;
    int b = bh / NHEADS, h = bh % NHEADS;
    const float* q  = g_qkv + (size_t)b * SEQ * LDA + h * HDIM;
    const float* kx = g_qkv + (size_t)b * SEQ * LDA + DMODEL + h * HDIM;
    float* out = g_qk + (size_t)bh * SEQ * SEQ;

    int tid = threadIdx.x;
    int tx = tid % 16, ty = tid / 16;
    int bm = blockIdx.y * BM, bn = blockIdx.x * BN;

    float acc[8][8];
#pragma unroll
    for (int i = 0; i < 8; i++)
#pragma unroll
        for (int j = 0; j < 8; j++) acc[i][j] = 0.f;

    for (int k0 = 0; k0 < HDIM; k0 += BK) {
#pragma unroll
        for (int e = tid; e < 512; e += 256) {
            int row = e >> 2, c4 = e & 3;
            float4 a = *(const float4*)(q + (size_t)(bm + row) * LDA + k0 + c4 * 4);
            Qs[c4 * 4 + 0][row] = a.x; Qs[c4 * 4 + 1][row] = a.y;
            Qs[c4 * 4 + 2][row] = a.z; Qs[c4 * 4 + 3][row] = a.w;
            float4 w = *(const float4*)(kx + (size_t)(bn + row) * LDA + k0 + c4 * 4);
            Ks[c4 * 4 + 0][row] = w.x; Ks[c4 * 4 + 1][row] = w.y;
            Ks[c4 * 4 + 2][row] = w.z; Ks[c4 * 4 + 3][row] = w.w;
        }
        __syncthreads();
#pragma unroll
        for (int kk = 0; kk < BK; kk++) {
            float a[8], w[8];
#pragma unroll
            for (int i = 0; i < 8; i++) a[i] = Qs[kk][ty * 8 + i];
#pragma unroll
            for (int j = 0; j < 8; j++) w[j] = Ks[kk][tx * 8 + j];
#pragma unroll
            for (int i = 0; i < 8; i++)
#pragma unroll
                for (int j = 0; j < 8; j++) acc[i][j] = fmaf(a[i], w[j], acc[i][j]);
        }
        __syncthreads();
    }

#pragma unroll
    for (int i = 0; i < 8; i++) {
        int n = bm + ty * 8 + i;
#pragma unroll
        for (int j = 0; j < 8; j++)
            out[(size_t)n * SEQ + bn + tx * 8 + j] = acc[i][j];
    }
}

// ---------------------------------------------------------------------------
// Softmax over last dim of qk*SCALE -> attn_mean (written to d_out region).
// One 256-thread block per row (row length SEQ=1024), row cached in smem.
// ---------------------------------------------------------------------------
__global__ void softmax_kernel(const float* __restrict__ qk, float* __restrict__ am) {
    size_t row = blockIdx.x;
    const float* in = qk + row * SEQ;
    float* out = am + row * SEQ;
    int tid = threadIdx.x;
    __shared__ float buf[SEQ];
    __shared__ float red[256];

    float m = -1e30f;
    for (int i = tid; i < SEQ; i += 256) {
        float v = in[i] * QK_SCALE;
        buf[i] = v;
        m = fmaxf(m, v);
    }
    red[tid] = m; __syncthreads();
    for (int k = 128; k > 0; k >>= 1) { if (tid < k) red[tid] = fmaxf(red[tid], red[tid + k]); __syncthreads(); }
    m = red[0]; __syncthreads();

    float s = 0.f;
    for (int i = tid; i < SEQ; i += 256) {
        float e = expf(buf[i] - m);
        buf[i] = e;
        s += e;
    }
    red[tid] = s; __syncthreads();
    for (int k = 128; k > 0; k >>= 1) { if (tid < k) red[tid] += red[tid + k]; __syncthreads(); }
    float inv = 1.0f / red[0];
    __syncthreads();

    for (int i = tid; i < SEQ; i += 256) out[i] = buf[i] * inv;
}

// ---------------------------------------------------------------------------
// Uncertainty: u[b,g,n,m] = sigmoid( sum_h qk[b,h,n,m]*cw[g,h] + cb[g] )
// One thread per (b,n,m); 12 strided loads (coalesced along m), 12 outputs.
// ---------------------------------------------------------------------------
__global__ void uncert_kernel(const float* __restrict__ qk, const float* __restrict__ cw,
                              const float* __restrict__ cb, float* __restrict__ uout) {
    __shared__ float w[NHEADS * NHEADS];
    __shared__ float bsh[NHEADS];
    int tid = threadIdx.x;
    if (tid < NHEADS * NHEADS) w[tid] = cw[tid];
    if (tid < NHEADS) bsh[tid] = cb[tid];
    __syncthreads();

    size_t idx = (size_t)blockIdx.x * blockDim.x + tid;   // over B*SEQ*SEQ
    if (idx >= (size_t)BDIM * SEQ * SEQ) return;
    size_t m = idx % SEQ;
    size_t bn = idx / SEQ;
    size_t n = bn % SEQ;
    size_t b = bn / SEQ;

    size_t base = ((size_t)b * NHEADS * SEQ + n) * SEQ + m;  // (b, h=0, n, m)
    const size_t hs = (size_t)SEQ * SEQ;

    float qv[NHEADS];
#pragma unroll
    for (int h = 0; h < NHEADS; h++) qv[h] = qk[base + (size_t)h * hs];

#pragma unroll
    for (int g = 0; g < NHEADS; g++) {
        float s = bsh[g];
#pragma unroll
        for (int h = 0; h < NHEADS; h++) s = fmaf(qv[h], w[g * NHEADS + h], s);
        uout[base + (size_t)g * hs] = 1.0f / (1.0f + expf(-s));
    }
}

// ---------------------------------------------------------------------------
// AV: out[b,h,n,d] = sum_m (am + u*r)[b,h,n,m] * v[b,h,m,d]
// attn built on the fly in the A-tile load. Output written transposed into
// [token, DMODEL] layout at column h*HDIM.
// ---------------------------------------------------------------------------
__global__ __launch_bounds__(256)
void av_kernel(const float* __restrict__ am, const float* __restrict__ u,
               const float* __restrict__ r, float* __restrict__ outp) {
    constexpr int BM = 128, BN = 64, BK = 16;
    constexpr int LDV = 3 * DMODEL;
    __shared__ float Ps[BK][BM + 4];
    __shared__ float Vs[BK][BN];
    int bh = blockIdx.z;
    int b = bh / NHEADS, h = bh % NHEADS;
    const float* amb = am + (size_t)bh * SEQ * SEQ;
    const float* ub  = u  + (size_t)bh * SEQ * SEQ;
    const float* rb  = r  + (size_t)bh * SEQ * SEQ;
    const float* v = g_qkv + (size_t)b * SEQ * LDV + 2 * DMODEL + h * HDIM;

    int tid = threadIdx.x;
    int tx = tid % 16, ty = tid / 16;
    int bm = blockIdx.y * BM;

    float acc[8][4];
#pragma unroll
    for (int i = 0; i < 8; i++)
#pragma unroll
        for (int j = 0; j < 4; j++) acc[i][j] = 0.f;

    for (int k0 = 0; k0 < SEQ; k0 += BK) {
#pragma unroll
        for (int e = tid; e < 512; e += 256) {
            int row = e >> 2, c4 = e & 3;
            size_t off = (size_t)(bm + row) * SEQ + k0 + c4 * 4;
            float4 a  = *(const float4*)(amb + off);
            float4 uu = *(const float4*)(ub + off);
            float4 rr = *(const float4*)(rb + off);
            Ps[c4 * 4 + 0][row] = fmaf(uu.x, rr.x, a.x);
            Ps[c4 * 4 + 1][row] = fmaf(uu.y, rr.y, a.y);
            Ps[c4 * 4 + 2][row] = fmaf(uu.z, rr.z, a.z);
            Ps[c4 * 4 + 3][row] = fmaf(uu.w, rr.w, a.w);
        }
        {
            int row = tid / 16, c4 = tid % 16;
            float4 vv = *(const float4*)(v + (size_t)(k0 + row) * LDV + c4 * 4);
            Vs[row][c4 * 4 + 0] = vv.x; Vs[row][c4 * 4 + 1] = vv.y;
            Vs[row][c4 * 4 + 2] = vv.z; Vs[row][c4 * 4 + 3] = vv.w;
        }
        __syncthreads();
#pragma unroll
        for (int kk = 0; kk < BK; kk++) {
            float a[8], w[4];
#pragma unroll
            for (int i = 0; i < 8; i++) a[i] = Ps[kk][ty * 8 + i];
#pragma unroll
            for (int j = 0; j < 4; j++) w[j] = Vs[kk][tx * 4 + j];
#pragma unroll
            for (int i = 0; i < 8; i++)
#pragma unroll
                for (int j = 0; j < 4; j++) acc[i][j] = fmaf(a[i], w[j], acc[i][j]);
        }
        __syncthreads();
    }

#pragma unroll
    for (int i = 0; i < 8; i++) {
        int n = bm + ty * 8 + i;
        float* orow = outp + (size_t)(b * SEQ + n) * DMODEL + h * HDIM;
#pragma unroll
        for (int j = 0; j < 4; j++) orow[tx * 4 + j] = acc[i][j];
    }
}

// ---------------------------------------------------------------------------
// Launch
// ---------------------------------------------------------------------------
extern "C" void kernel_launch(void* const* d_in, const int* in_sizes, int n_in,
                              void* d_out, int out_size) {
    const float* x      = (const float*)d_in[0];
    const float* r      = (const float*)d_in[1];
    const float* ln1_g  = (const float*)d_in[2];
    const float* ln1_b  = (const float*)d_in[3];
    const float* qkv_w  = (const float*)d_in[4];
    const float* qkv_b  = (const float*)d_in[5];
    const float* conv_w = (const float*)d_in[6];
    const float* conv_b = (const float*)d_in[7];
    const float* proj_w = (const float*)d_in[8];
    const float* proj_b = (const float*)d_in[9];
    const float* ln2_g  = (const float*)d_in[10];
    const float* ln2_b  = (const float*)d_in[11];
    const float* fc1_w  = (const float*)d_in[12];
    const float* fc1_b  = (const float*)d_in[13];
    const float* fc2_w  = (const float*)d_in[14];
    const float* fc2_b  = (const float*)d_in[15];

    float* out    = (float*)d_out;
    float* out_x  = out;                                              // [TTOK, DMODEL]
    float* out_am = out + (size_t)TTOK * DMODEL;                      // [B,H,N,N]
    float* out_u  = out_am + (size_t)BDIM * NHEADS * SEQ * SEQ;       // [B,H,N,N]

    // Symbol addresses: resolved once on the first (non-captured) call.
    static float *p_h = nullptr, *p_qkv = nullptr, *p_qk = nullptr,
                 *p_ao = nullptr, *p_x1 = nullptr, *p_mlp = nullptr;
    if (!p_h) {
        cudaGetSymbolAddress((void**)&p_h, g_h);
        cudaGetSymbolAddress((void**)&p_qkv, g_qkv);
        cudaGetSymbolAddress((void**)&p_qk, g_qk);
        cudaGetSymbolAddress((void**)&p_ao, g_attnout);
        cudaGetSymbolAddress((void**)&p_x1, g_x1);
        cudaGetSymbolAddress((void**)&p_mlp, g_mlp);
    }

    // 1. LN1
    ln_kernel<<<TTOK, 256>>>(x, ln1_g, ln1_b, p_h);

    // 2. QKV: [2048,768] @ [2304,768]^T
    gemm_nt<0, false><<<dim3(3 * DMODEL / 128, TTOK / 128), 256>>>(
        p_h, qkv_w, qkv_b, nullptr, p_qkv, TTOK, 3 * DMODEL, DMODEL);

    // 3. QK^T (raw logits)
    qk_kernel<<<dim3(SEQ / 128, SEQ / 128, BDIM * NHEADS), 256>>>();

    // 4. softmax -> attn_mean output
    softmax_kernel<<<BDIM * NHEADS * SEQ, 256>>>(p_qk, out_am);

    // 5. uncertainty -> output
    {
        size_t total = (size_t)BDIM * SEQ * SEQ;
        uncert_kernel<<<(unsigned)((total + 255) / 256), 256>>>(p_qk, conv_w, conv_b, out_u);
    }

    // 6. AV with fused attn = am + u*r
    av_kernel<<<dim3(1, SEQ / 128, BDIM * NHEADS), 256>>>(out_am, out_u, r, p_ao);

    // 7. proj + residual(x) -> x1
    gemm_nt<0, true><<<dim3(DMODEL / 128, TTOK / 128), 256>>>(
        p_ao, proj_w, proj_b, x, p_x1, TTOK, DMODEL, DMODEL);

    // 8. LN2
    ln_kernel<<<TTOK, 256>>>(p_x1, ln2_g, ln2_b, p_h);

    // 9. fc1 + gelu
    gemm_nt<1, false><<<dim3(DMLP / 128, TTOK / 128), 256>>>(
        p_h, fc1_w, fc1_b, nullptr, p_mlp, TTOK, DMLP, DMODEL);

    // 10. fc2 + residual(x1) -> x output
    gemm_nt<0, true><<<dim3(DMODEL / 128, TTOK / 128), 256>>>(
        p_mlp, fc2_w, fc2_b, p_x1, out_x, TTOK, DMODEL, DMLP);
}

// round 3
// speedup vs baseline: 1.5353x; 1.5353x over previous
#include <cuda_runtime.h>
#include <math.h>
#include <stdint.h>

// ---------------------------------------------------------------------------
// Problem constants
// ---------------------------------------------------------------------------
#define BDIM   2
#define SEQ    1024
#define DMODEL 768
#define NHEADS 12
#define HDIM   64
#define DMLP   3072
#define TTOK   (BDIM * SEQ)          // 2048 tokens
#define QK_SCALE 0.125f              // HDIM^-0.5

// ---------------------------------------------------------------------------
// Scratch (static __device__ globals: allocation-guard safe)
// ---------------------------------------------------------------------------
static __device__ __align__(16) float g_h[TTOK * DMODEL];              //  6 MB
static __device__ __align__(16) float g_qkv[TTOK * 3 * DMODEL];        // 18 MB
static __device__ __align__(16) float g_qk[(size_t)BDIM * NHEADS * SEQ * SEQ]; // 100 MB
static __device__ __align__(16) float g_attnout[TTOK * DMODEL];        //  6 MB
static __device__ __align__(16) float g_x1[TTOK * DMODEL];             //  6 MB
static __device__ __align__(16) float g_mlp[(size_t)TTOK * DMLP];      // 24 MB

// ---------------------------------------------------------------------------
// LayerNorm
// ---------------------------------------------------------------------------
__global__ void ln_kernel(const float* __restrict__ x, const float* __restrict__ g,
                          const float* __restrict__ b, float* __restrict__ out) {
    int row = blockIdx.x;
    const float* xr = x + (size_t)row * DMODEL;
    float* orow = out + (size_t)row * DMODEL;
    __shared__ float red[256];
    int tid = threadIdx.x;

    float s = 0.f;
    for (int i = tid; i < DMODEL; i += 256) s += xr[i];
    red[tid] = s; __syncthreads();
    for (int k = 128; k > 0; k >>= 1) { if (tid < k) red[tid] += red[tid + k]; __syncthreads(); }
    float mu = red[0] * (1.0f / DMODEL);
    __syncthreads();

    float v = 0.f;
    for (int i = tid; i < DMODEL; i += 256) { float d = xr[i] - mu; v += d * d; }
    red[tid] = v; __syncthreads();
    for (int k = 128; k > 0; k >>= 1) { if (tid < k) red[tid] += red[tid + k]; __syncthreads(); }
    float rstd = rsqrtf(red[0] * (1.0f / DMODEL) + 1e-5f);

    for (int i = tid; i < DMODEL; i += 256)
        orow[i] = (xr[i] - mu) * rstd * g[i] + b[i];
}

__device__ __forceinline__ float gelu_tanh(float x) {
    float x3 = x * x * x;
    float t = tanhf(0.7978845608028654f * (x + 0.044715f * x3));
    return 0.5f * x * (1.0f + t);
}

// ---------------------------------------------------------------------------
// tf32 helpers
// ---------------------------------------------------------------------------
__device__ __forceinline__ uint32_t f2tf32(float x) {
    uint32_t y;
    asm("cvt.rna.tf32.f32 %0, %1;" : "=r"(y) : "f"(x));
    return y;
}

__device__ __forceinline__ void mma_tf32(float c[4], const uint32_t a[4], const uint32_t b[2]) {
    asm volatile(
        "mma.sync.aligned.m16n8k8.row.col.f32.tf32.tf32.f32 "
        "{%0,%1,%2,%3}, {%4,%5,%6,%7}, {%8,%9}, {%0,%1,%2,%3};\n"
        : "+f"(c[0]), "+f"(c[1]), "+f"(c[2]), "+f"(c[3])
        : "r"(a[0]), "r"(a[1]), "r"(a[2]), "r"(a[3]), "r"(b[0]), "r"(b[1]));
}

// ---------------------------------------------------------------------------
// tf32 tensor-core NT GEMM: C[M,N] = A[M,K] @ W[N,K]^T + bias (+gelu) (+res)
// Block tile 128x128x32, 8 warps (2x4), warp tile 64x32 via 4x4 m16n8k8 mmas.
// M,N multiples of 128; K multiple of 32.
// ---------------------------------------------------------------------------
template <int ACT, bool RES>
__global__ __launch_bounds__(256)
void gemm_tf32(const float* __restrict__ A, const float* __restrict__ W,
               const float* __restrict__ bias, const float* __restrict__ res,
               float* __restrict__ C, int M, int N, int K) {
    constexpr int BM = 128, BN = 128, BK = 32;
    __shared__ uint32_t As[BK][BM + 4];
    __shared__ uint32_t Ws[BK][BN + 4];

    int tid = threadIdx.x;
    int lane = tid & 31;
    int warp = tid >> 5;
    int warpM = warp >> 2;        // 0..1  -> 64-row band
    int warpN = warp & 3;         // 0..3  -> 32-col band
    int qk_ = lane & 3;           // threadID_in_group
    int qr = lane >> 2;           // groupID

    const float* Ab = A + (size_t)(blockIdx.y * BM) * K;
    const float* Wb = W + (size_t)(blockIdx.x * BN) * K;

    float acc[4][4][4];           // [mt][nt][frag]
#pragma unroll
    for (int i = 0; i < 4; i++)
#pragma unroll
        for (int j = 0; j < 4; j++)
#pragma unroll
            for (int f = 0; f < 4; f++) acc[i][j][f] = 0.f;

    for (int k0 = 0; k0 < K; k0 += BK) {
        // Stage tiles (converted to tf32). 128 rows x 32 cols = 1024 float4-loads/2.
#pragma unroll
        for (int e = tid; e < 1024; e += 256) {
            int row = e >> 3, c4 = e & 7;
            float4 a = *(const float4*)(Ab + (size_t)row * K + k0 + c4 * 4);
            As[c4 * 4 + 0][row] = f2tf32(a.x); As[c4 * 4 + 1][row] = f2tf32(a.y);
            As[c4 * 4 + 2][row] = f2tf32(a.z); As[c4 * 4 + 3][row] = f2tf32(a.w);
            float4 w = *(const float4*)(Wb + (size_t)row * K + k0 + c4 * 4);
            Ws[c4 * 4 + 0][row] = f2tf32(w.x); Ws[c4 * 4 + 1][row] = f2tf32(w.y);
            Ws[c4 * 4 + 2][row] = f2tf32(w.z); Ws[c4 * 4 + 3][row] = f2tf32(w.w);
        }
        __syncthreads();

#pragma unroll
        for (int kk = 0; kk < 4; kk++) {
            int kb = kk * 8;
            uint32_t afrag[4][4];
            uint32_t bfrag[4][2];
#pragma unroll
            for (int mt = 0; mt < 4; mt++) {
                int rb = warpM * 64 + mt * 16 + qr;
                afrag[mt][0] = As[kb + qk_][rb];
                afrag[mt][1] = As[kb + qk_][rb + 8];
                afrag[mt][2] = As[kb + qk_ + 4][rb];
                afrag[mt][3] = As[kb + qk_ + 4][rb + 8];
            }
#pragma unroll
            for (int nt = 0; nt < 4; nt++) {
                int cb = warpN * 32 + nt * 8 + qr;
                bfrag[nt][0] = Ws[kb + qk_][cb];
                bfrag[nt][1] = Ws[kb + qk_ + 4][cb];
            }
#pragma unroll
            for (int mt = 0; mt < 4; mt++)
#pragma unroll
                for (int nt = 0; nt < 4; nt++)
                    mma_tf32(acc[mt][nt], afrag[mt], bfrag[nt]);
        }
        __syncthreads();
    }

    // Epilogue: c0/c1 at (row, 2q..2q+1), c2/c3 at (row+8, ...)
#pragma unroll
    for (int mt = 0; mt < 4; mt++) {
        int r0 = blockIdx.y * BM + warpM * 64 + mt * 16 + qr;
#pragma unroll
        for (int nt = 0; nt < 4; nt++) {
            int col = blockIdx.x * BN + warpN * 32 + nt * 8 + 2 * qk_;
            float b0 = bias[col], b1 = bias[col + 1];
            float v0 = acc[mt][nt][0] + b0;
            float v1 = acc[mt][nt][1] + b1;
            float v2 = acc[mt][nt][2] + b0;
            float v3 = acc[mt][nt][3] + b1;
            if (ACT == 1) { v0 = gelu_tanh(v0); v1 = gelu_tanh(v1); v2 = gelu_tanh(v2); v3 = gelu_tanh(v3); }
            size_t o0 = (size_t)r0 * N + col;
            size_t o1 = (size_t)(r0 + 8) * N + col;
            if (RES) {
                v0 += res[o0]; v1 += res[o0 + 1];
                v2 += res[o1]; v3 += res[o1 + 1];
            }
            *(float2*)(C + o0) = make_float2(v0, v1);
            *(float2*)(C + o1) = make_float2(v2, v3);
        }
    }
}

// ---------------------------------------------------------------------------
// Batched QK^T (exact fp32): per (b,h): qk[n,m] = sum_d q[n,d]*k[m,d]
// ---------------------------------------------------------------------------
__global__ __launch_bounds__(256)
void qk_kernel() {
    constexpr int BM = 128, BN = 128, BK = 16;
    constexpr int LDA = 3 * DMODEL;
    __shared__ float Qs[BK][BM + 4];
    __shared__ float Ks[BK][BN + 4];
    int bh = blockIdx.z;
    int b = bh / NHEADS, h = bh % NHEADS;
    const float* q  = g_qkv + (size_t)b * SEQ * LDA + h * HDIM;
    const float* kx = g_qkv + (size_t)b * SEQ * LDA + DMODEL + h * HDIM;
    float* out = g_qk + (size_t)bh * SEQ * SEQ;

    int tid = threadIdx.x;
    int tx = tid % 16, ty = tid / 16;
    int bm = blockIdx.y * BM, bn = blockIdx.x * BN;

    float acc[8][8];
#pragma unroll
    for (int i = 0; i < 8; i++)
#pragma unroll
        for (int j = 0; j < 8; j++) acc[i][j] = 0.f;

    for (int k0 = 0; k0 < HDIM; k0 += BK) {
#pragma unroll
        for (int e = tid; e < 512; e += 256) {
            int row = e >> 2, c4 = e & 3;
            float4 a = *(const float4*)(q + (size_t)(bm + row) * LDA + k0 + c4 * 4);
            Qs[c4 * 4 + 0][row] = a.x; Qs[c4 * 4 + 1][row] = a.y;
            Qs[c4 * 4 + 2][row] = a.z; Qs[c4 * 4 + 3][row] = a.w;
            float4 w = *(const float4*)(kx + (size_t)(bn + row) * LDA + k0 + c4 * 4);
            Ks[c4 * 4 + 0][row] = w.x; Ks[c4 * 4 + 1][row] = w.y;
            Ks[c4 * 4 + 2][row] = w.z; Ks[c4 * 4 + 3][row] = w.w;
        }
        __syncthreads();
#pragma unroll
        for (int kk = 0; kk < BK; kk++) {
            float a[8], w[8];
#pragma unroll
            for (int i = 0; i < 8; i++) a[i] = Qs[kk][ty * 8 + i];
#pragma unroll
            for (int j = 0; j < 8; j++) w[j] = Ks[kk][tx * 8 + j];
#pragma unroll
            for (int i = 0; i < 8; i++)
#pragma unroll
                for (int j = 0; j < 8; j++) acc[i][j] = fmaf(a[i], w[j], acc[i][j]);
        }
        __syncthreads();
    }

#pragma unroll
    for (int i = 0; i < 8; i++) {
        int n = bm + ty * 8 + i;
#pragma unroll
        for (int j = 0; j < 8; j++)
            out[(size_t)n * SEQ + bn + tx * 8 + j] = acc[i][j];
    }
}

// ---------------------------------------------------------------------------
// Softmax -> attn_mean (d_out region)
// ---------------------------------------------------------------------------
__global__ void softmax_kernel(const float* __restrict__ qk, float* __restrict__ am) {
    size_t row = blockIdx.x;
    const float* in = qk + row * SEQ;
    float* out = am + row * SEQ;
    int tid = threadIdx.x;
    __shared__ float buf[SEQ];
    __shared__ float red[256];

    float m = -1e30f;
    for (int i = tid; i < SEQ; i += 256) {
        float v = in[i] * QK_SCALE;
        buf[i] = v;
        m = fmaxf(m, v);
    }
    red[tid] = m; __syncthreads();
    for (int k = 128; k > 0; k >>= 1) { if (tid < k) red[tid] = fmaxf(red[tid], red[tid + k]); __syncthreads(); }
    m = red[0]; __syncthreads();

    float s = 0.f;
    for (int i = tid; i < SEQ; i += 256) {
        float e = expf(buf[i] - m);
        buf[i] = e;
        s += e;
    }
    red[tid] = s; __syncthreads();
    for (int k = 128; k > 0; k >>= 1) { if (tid < k) red[tid] += red[tid + k]; __syncthreads(); }
    float inv = 1.0f / red[0];
    __syncthreads();

    for (int i = tid; i < SEQ; i += 256) out[i] = buf[i] * inv;
}

// ---------------------------------------------------------------------------
// Uncertainty
// ---------------------------------------------------------------------------
__global__ void uncert_kernel(const float* __restrict__ qk, const float* __restrict__ cw,
                              const float* __restrict__ cb, float* __restrict__ uout) {
    __shared__ float w[NHEADS * NHEADS];
    __shared__ float bsh[NHEADS];
    int tid = threadIdx.x;
    if (tid < NHEADS * NHEADS) w[tid] = cw[tid];
    if (tid < NHEADS) bsh[tid] = cb[tid];
    __syncthreads();

    size_t idx = (size_t)blockIdx.x * blockDim.x + tid;
    if (idx >= (size_t)BDIM * SEQ * SEQ) return;
    size_t m = idx % SEQ;
    size_t bn = idx / SEQ;
    size_t n = bn % SEQ;
    size_t b = bn / SEQ;

    size_t base = ((size_t)b * NHEADS * SEQ + n) * SEQ + m;
    const size_t hs = (size_t)SEQ * SEQ;

    float qv[NHEADS];
#pragma unroll
    for (int h = 0; h < NHEADS; h++) qv[h] = qk[base + (size_t)h * hs];

#pragma unroll
    for (int g = 0; g < NHEADS; g++) {
        float s = bsh[g];
#pragma unroll
        for (int h = 0; h < NHEADS; h++) s = fmaf(qv[h], w[g * NHEADS + h], s);
        uout[base + (size_t)g * hs] = 1.0f / (1.0f + expf(-s));
    }
}

// ---------------------------------------------------------------------------
// AV (exact fp32), attn = am + u*r fused in the A-tile load
// ---------------------------------------------------------------------------
__global__ __launch_bounds__(256)
void av_kernel(const float* __restrict__ am, const float* __restrict__ u,
               const float* __restrict__ r, float* __restrict__ outp) {
    constexpr int BM = 128, BN = 64, BK = 16;
    constexpr int LDV = 3 * DMODEL;
    __shared__ float Ps[BK][BM + 4];
    __shared__ float Vs[BK][BN];
    int bh = blockIdx.z;
    int b = bh / NHEADS, h = bh % NHEADS;
    const float* amb = am + (size_t)bh * SEQ * SEQ;
    const float* ub  = u  + (size_t)bh * SEQ * SEQ;
    const float* rb  = r  + (size_t)bh * SEQ * SEQ;
    const float* v = g_qkv + (size_t)b * SEQ * LDV + 2 * DMODEL + h * HDIM;

    int tid = threadIdx.x;
    int tx = tid % 16, ty = tid / 16;
    int bm = blockIdx.y * BM;

    float acc[8][4];
#pragma unroll
    for (int i = 0; i < 8; i++)
#pragma unroll
        for (int j = 0; j < 4; j++) acc[i][j] = 0.f;

    for (int k0 = 0; k0 < SEQ; k0 += BK) {
#pragma unroll
        for (int e = tid; e < 512; e += 256) {
            int row = e >> 2, c4 = e & 3;
            size_t off = (size_t)(bm + row) * SEQ + k0 + c4 * 4;
            float4 a  = *(const float4*)(amb + off);
            float4 uu = *(const float4*)(ub + off);
            float4 rr = *(const float4*)(rb + off);
            Ps[c4 * 4 + 0][row] = fmaf(uu.x, rr.x, a.x);
            Ps[c4 * 4 + 1][row] = fmaf(uu.y, rr.y, a.y);
            Ps[c4 * 4 + 2][row] = fmaf(uu.z, rr.z, a.z);
            Ps[c4 * 4 + 3][row] = fmaf(uu.w, rr.w, a.w);
        }
        {
            int row = tid / 16, c4 = tid % 16;
            float4 vv = *(const float4*)(v + (size_t)(k0 + row) * LDV + c4 * 4);
            Vs[row][c4 * 4 + 0] = vv.x; Vs[row][c4 * 4 + 1] = vv.y;
            Vs[row][c4 * 4 + 2] = vv.z; Vs[row][c4 * 4 + 3] = vv.w;
        }
        __syncthreads();
#pragma unroll
        for (int kk = 0; kk < BK; kk++) {
            float a[8], w[4];
#pragma unroll
            for (int i = 0; i < 8; i++) a[i] = Ps[kk][ty * 8 + i];
#pragma unroll
            for (int j = 0; j < 4; j++) w[j] = Vs[kk][tx * 4 + j];
#pragma unroll
            for (int i = 0; i < 8; i++)
#pragma unroll
                for (int j = 0; j < 4; j++) acc[i][j] = fmaf(a[i], w[j], acc[i][j]);
        }
        __syncthreads();
    }

#pragma unroll
    for (int i = 0; i < 8; i++) {
        int n = bm + ty * 8 + i;
        float* orow = outp + (size_t)(b * SEQ + n) * DMODEL + h * HDIM;
#pragma unroll
        for (int j = 0; j < 4; j++) orow[tx * 4 + j] = acc[i][j];
    }
}

// ---------------------------------------------------------------------------
// Launch
// ---------------------------------------------------------------------------
extern "C" void kernel_launch(void* const* d_in, const int* in_sizes, int n_in,
                              void* d_out, int out_size) {
    const float* x      = (const float*)d_in[0];
    const float* r      = (const float*)d_in[1];
    const float* ln1_g  = (const float*)d_in[2];
    const float* ln1_b  = (const float*)d_in[3];
    const float* qkv_w  = (const float*)d_in[4];
    const float* qkv_b  = (const float*)d_in[5];
    const float* conv_w = (const float*)d_in[6];
    const float* conv_b = (const float*)d_in[7];
    const float* proj_w = (const float*)d_in[8];
    const float* proj_b = (const float*)d_in[9];
    const float* ln2_g  = (const float*)d_in[10];
    const float* ln2_b  = (const float*)d_in[11];
    const float* fc1_w  = (const float*)d_in[12];
    const float* fc1_b  = (const float*)d_in[13];
    const float* fc2_w  = (const float*)d_in[14];
    const float* fc2_b  = (const float*)d_in[15];

    float* out    = (float*)d_out;
    float* out_x  = out;
    float* out_am = out + (size_t)TTOK * DMODEL;
    float* out_u  = out_am + (size_t)BDIM * NHEADS * SEQ * SEQ;

    static float *p_h = nullptr, *p_qkv = nullptr, *p_qk = nullptr,
                 *p_ao = nullptr, *p_x1 = nullptr, *p_mlp = nullptr;
    if (!p_h) {
        cudaGetSymbolAddress((void**)&p_h, g_h);
        cudaGetSymbolAddress((void**)&p_qkv, g_qkv);
        cudaGetSymbolAddress((void**)&p_qk, g_qk);
        cudaGetSymbolAddress((void**)&p_ao, g_attnout);
        cudaGetSymbolAddress((void**)&p_x1, g_x1);
        cudaGetSymbolAddress((void**)&p_mlp, g_mlp);
    }

    // 1. LN1
    ln_kernel<<<TTOK, 256>>>(x, ln1_g, ln1_b, p_h);

    // 2. QKV (tf32 tensor cores)
    gemm_tf32<0, false><<<dim3(3 * DMODEL / 128, TTOK / 128), 256>>>(
        p_h, qkv_w, qkv_b, nullptr, p_qkv, TTOK, 3 * DMODEL, DMODEL);

    // 3. QK^T raw logits (exact fp32 for softmax/uncertainty fidelity)
    qk_kernel<<<dim3(SEQ / 128, SEQ / 128, BDIM * NHEADS), 256>>>();

    // 4. softmax -> attn_mean
    softmax_kernel<<<BDIM * NHEADS * SEQ, 256>>>(p_qk, out_am);

    // 5. uncertainty
    {
        size_t total = (size_t)BDIM * SEQ * SEQ;
        uncert_kernel<<<(unsigned)((total + 255) / 256), 256>>>(p_qk, conv_w, conv_b, out_u);
    }

    // 6. AV fused attn = am + u*r
    av_kernel<<<dim3(1, SEQ / 128, BDIM * NHEADS), 256>>>(out_am, out_u, r, p_ao);

    // 7. proj + residual(x) (tf32)
    gemm_tf32<0, true><<<dim3(DMODEL / 128, TTOK / 128), 256>>>(
        p_ao, proj_w, proj_b, x, p_x1, TTOK, DMODEL, DMODEL);

    // 8. LN2
    ln_kernel<<<TTOK, 256>>>(p_x1, ln2_g, ln2_b, p_h);

    // 9. fc1 + gelu (tf32)
    gemm_tf32<1, false><<<dim3(DMLP / 128, TTOK / 128), 256>>>(
        p_h, fc1_w, fc1_b, nullptr, p_mlp, TTOK, DMLP, DMODEL);

    // 10. fc2 + residual(x1) (tf32)
    gemm_tf32<0, true><<<dim3(DMODEL / 128, TTOK / 128), 256>>>(
        p_mlp, fc2_w, fc2_b, p_x1, out_x, TTOK, DMODEL, DMLP);
}

// round 5
// speedup vs baseline: 1.6454x; 1.0718x over previous
#include <cuda_runtime.h>
#include <math.h>
#include <stdint.h>

// ---------------------------------------------------------------------------
// Problem constants
// ---------------------------------------------------------------------------
#define BDIM   2
#define SEQ    1024
#define DMODEL 768
#define NHEADS 12
#define HDIM   64
#define DMLP   3072
#define TTOK   (BDIM * SEQ)
#define QK_SCALE 0.125f

// ---------------------------------------------------------------------------
// Scratch
// ---------------------------------------------------------------------------
static __device__ __align__(16) float g_h[TTOK * DMODEL];
static __device__ __align__(16) float g_qkv[TTOK * 3 * DMODEL];
static __device__ __align__(16) float g_qk[(size_t)BDIM * NHEADS * SEQ * SEQ]; // logits, then attn (in place)
static __device__ __align__(16) float g_attnout[TTOK * DMODEL];
static __device__ __align__(16) float g_x1[TTOK * DMODEL];
static __device__ __align__(16) float g_mlp[(size_t)TTOK * DMLP];

// ---------------------------------------------------------------------------
// LayerNorm
// ---------------------------------------------------------------------------
__global__ void ln_kernel(const float* __restrict__ x, const float* __restrict__ g,
                          const float* __restrict__ b, float* __restrict__ out) {
    int row = blockIdx.x;
    const float* xr = x + (size_t)row * DMODEL;
    float* orow = out + (size_t)row * DMODEL;
    __shared__ float red[256];
    int tid = threadIdx.x;

    float s = 0.f;
    for (int i = tid; i < DMODEL; i += 256) s += xr[i];
    red[tid] = s; __syncthreads();
    for (int k = 128; k > 0; k >>= 1) { if (tid < k) red[tid] += red[tid + k]; __syncthreads(); }
    float mu = red[0] * (1.0f / DMODEL);
    __syncthreads();

    float v = 0.f;
    for (int i = tid; i < DMODEL; i += 256) { float d = xr[i] - mu; v += d * d; }
    red[tid] = v; __syncthreads();
    for (int k = 128; k > 0; k >>= 1) { if (tid < k) red[tid] += red[tid + k]; __syncthreads(); }
    float rstd = rsqrtf(red[0] * (1.0f / DMODEL) + 1e-5f);

    for (int i = tid; i < DMODEL; i += 256)
        orow[i] = (xr[i] - mu) * rstd * g[i] + b[i];
}

__device__ __forceinline__ float gelu_tanh(float x) {
    float x3 = x * x * x;
    float t = tanhf(0.7978845608028654f * (x + 0.044715f * x3));
    return 0.5f * x * (1.0f + t);
}

// ---------------------------------------------------------------------------
// tf32 helpers
// ---------------------------------------------------------------------------
__device__ __forceinline__ uint32_t f2tf32(float x) {
    uint32_t y;
    asm("cvt.rna.tf32.f32 %0, %1;" : "=r"(y) : "f"(x));
    return y;
}

__device__ __forceinline__ void mma_tf32(float c[4], const uint32_t a[4], const uint32_t b[2]) {
    asm volatile(
        "mma.sync.aligned.m16n8k8.row.col.f32.tf32.tf32.f32 "
        "{%0,%1,%2,%3}, {%4,%5,%6,%7}, {%8,%9}, {%0,%1,%2,%3};\n"
        : "+f"(c[0]), "+f"(c[1]), "+f"(c[2]), "+f"(c[3])
        : "r"(a[0]), "r"(a[1]), "r"(a[2]), "r"(a[3]), "r"(b[0]), "r"(b[1]));
}

// ---------------------------------------------------------------------------
// tf32 NT GEMM (unchanged from round 2)
// ---------------------------------------------------------------------------
template <int ACT, bool RES>
__global__ __launch_bounds__(256)
void gemm_tf32(const float* __restrict__ A, const float* __restrict__ W,
               const float* __restrict__ bias, const float* __restrict__ res,
               float* __restrict__ C, int M, int N, int K) {
    constexpr int BM = 128, BN = 128, BK = 32;
    __shared__ uint32_t As[BK][BM + 4];
    __shared__ uint32_t Ws[BK][BN + 4];

    int tid = threadIdx.x;
    int lane = tid & 31;
    int warp = tid >> 5;
    int warpM = warp >> 2;
    int warpN = warp & 3;
    int qk_ = lane & 3;
    int qr = lane >> 2;

    const float* Ab = A + (size_t)(blockIdx.y * BM) * K;
    const float* Wb = W + (size_t)(blockIdx.x * BN) * K;

    float acc[4][4][4];
#pragma unroll
    for (int i = 0; i < 4; i++)
#pragma unroll
        for (int j = 0; j < 4; j++)
#pragma unroll
            for (int f = 0; f < 4; f++) acc[i][j][f] = 0.f;

    for (int k0 = 0; k0 < K; k0 += BK) {
#pragma unroll
        for (int e = tid; e < 1024; e += 256) {
            int row = e >> 3, c4 = e & 7;
            float4 a = *(const float4*)(Ab + (size_t)row * K + k0 + c4 * 4);
            As[c4 * 4 + 0][row] = f2tf32(a.x); As[c4 * 4 + 1][row] = f2tf32(a.y);
            As[c4 * 4 + 2][row] = f2tf32(a.z); As[c4 * 4 + 3][row] = f2tf32(a.w);
            float4 w = *(const float4*)(Wb + (size_t)row * K + k0 + c4 * 4);
            Ws[c4 * 4 + 0][row] = f2tf32(w.x); Ws[c4 * 4 + 1][row] = f2tf32(w.y);
            Ws[c4 * 4 + 2][row] = f2tf32(w.z); Ws[c4 * 4 + 3][row] = f2tf32(w.w);
        }
        __syncthreads();

#pragma unroll
        for (int kk = 0; kk < 4; kk++) {
            int kb = kk * 8;
            uint32_t afrag[4][4];
            uint32_t bfrag[4][2];
#pragma unroll
            for (int mt = 0; mt < 4; mt++) {
                int rb = warpM * 64 + mt * 16 + qr;
                afrag[mt][0] = As[kb + qk_][rb];
                afrag[mt][1] = As[kb + qk_][rb + 8];
                afrag[mt][2] = As[kb + qk_ + 4][rb];
                afrag[mt][3] = As[kb + qk_ + 4][rb + 8];
            }
#pragma unroll
            for (int nt = 0; nt < 4; nt++) {
                int cb = warpN * 32 + nt * 8 + qr;
                bfrag[nt][0] = Ws[kb + qk_][cb];
                bfrag[nt][1] = Ws[kb + qk_ + 4][cb];
            }
#pragma unroll
            for (int mt = 0; mt < 4; mt++)
#pragma unroll
                for (int nt = 0; nt < 4; nt++)
                    mma_tf32(acc[mt][nt], afrag[mt], bfrag[nt]);
        }
        __syncthreads();
    }

#pragma unroll
    for (int mt = 0; mt < 4; mt++) {
        int r0 = blockIdx.y * BM + warpM * 64 + mt * 16 + qr;
#pragma unroll
        for (int nt = 0; nt < 4; nt++) {
            int col = blockIdx.x * BN + warpN * 32 + nt * 8 + 2 * qk_;
            float b0 = bias[col], b1 = bias[col + 1];
            float v0 = acc[mt][nt][0] + b0;
            float v1 = acc[mt][nt][1] + b1;
            float v2 = acc[mt][nt][2] + b0;
            float v3 = acc[mt][nt][3] + b1;
            if (ACT == 1) { v0 = gelu_tanh(v0); v1 = gelu_tanh(v1); v2 = gelu_tanh(v2); v3 = gelu_tanh(v3); }
            size_t o0 = (size_t)r0 * N + col;
            size_t o1 = (size_t)(r0 + 8) * N + col;
            if (RES) {
                v0 += res[o0]; v1 += res[o0 + 1];
                v2 += res[o1]; v3 += res[o1 + 1];
            }
            *(float2*)(C + o0) = make_float2(v0, v1);
            *(float2*)(C + o1) = make_float2(v2, v3);
        }
    }
}

// ---------------------------------------------------------------------------
// Batched QK^T (exact fp32 FFMA — protects attn_mean/uncertainty error budget)
// ---------------------------------------------------------------------------
__global__ __launch_bounds__(256)
void qk_kernel() {
    constexpr int BM = 128, BN = 128, BK = 16;
    constexpr int LDA = 3 * DMODEL;
    __shared__ float Qs[BK][BM + 4];
    __shared__ float Ks[BK][BN + 4];
    int bh = blockIdx.z;
    int b = bh / NHEADS, h = bh % NHEADS;
    const float* q  = g_qkv + (size_t)b * SEQ * LDA + h * HDIM;
    const float* kx = g_qkv + (size_t)b * SEQ * LDA + DMODEL + h * HDIM;
    float* out = g_qk + (size_t)bh * SEQ * SEQ;

    int tid = threadIdx.x;
    int tx = tid % 16, ty = tid / 16;
    int bm = blockIdx.y * BM, bn = blockIdx.x * BN;

    float acc[8][8];
#pragma unroll
    for (int i = 0; i < 8; i++)
#pragma unroll
        for (int j = 0; j < 8; j++) acc[i][j] = 0.f;

    for (int k0 = 0; k0 < HDIM; k0 += BK) {
#pragma unroll
        for (int e = tid; e < 512; e += 256) {
            int row = e >> 2, c4 = e & 3;
            float4 a = *(const float4*)(q + (size_t)(bm + row) * LDA + k0 + c4 * 4);
            Qs[c4 * 4 + 0][row] = a.x; Qs[c4 * 4 + 1][row] = a.y;
            Qs[c4 * 4 + 2][row] = a.z; Qs[c4 * 4 + 3][row] = a.w;
            float4 w = *(const float4*)(kx + (size_t)(bn + row) * LDA + k0 + c4 * 4);
            Ks[c4 * 4 + 0][row] = w.x; Ks[c4 * 4 + 1][row] = w.y;
            Ks[c4 * 4 + 2][row] = w.z; Ks[c4 * 4 + 3][row] = w.w;
        }
        __syncthreads();
#pragma unroll
        for (int kk = 0; kk < BK; kk++) {
            float a[8], w[8];
#pragma unroll
            for (int i = 0; i < 8; i++) a[i] = Qs[kk][ty * 8 + i];
#pragma unroll
            for (int j = 0; j < 8; j++) w[j] = Ks[kk][tx * 8 + j];
#pragma unroll
            for (int i = 0; i < 8; i++)
#pragma unroll
                for (int j = 0; j < 8; j++) acc[i][j] = fmaf(a[i], w[j], acc[i][j]);
        }
        __syncthreads();
    }

#pragma unroll
    for (int i = 0; i < 8; i++) {
        int n = bm + ty * 8 + i;
#pragma unroll
        for (int j = 0; j < 8; j++)
            out[(size_t)n * SEQ + bn + tx * 8 + j] = acc[i][j];
    }
}

// ---------------------------------------------------------------------------
// Fused softmax + uncertainty + attn-build.
// One block per (b, n). 384 threads = 12 warps (warp h owns head h's row).
// smem: buf[12][LD] (raw logits -> exp), ubuf[12][LD] (sigmoid outputs).
// Writes: am (d_out), u (d_out), attn = am + u*r (in place into g_qk).
// ---------------------------------------------------------------------------
#define FLD (SEQ + 4)
__global__ __launch_bounds__(384)
void fused_su_kernel(const float* __restrict__ r, const float* __restrict__ cw,
                     const float* __restrict__ cb,
                     float* __restrict__ am_out, float* __restrict__ u_out) {
    extern __shared__ float sm[];
    float* buf  = sm;                      // [NHEADS][FLD]
    float* ubuf = sm + NHEADS * FLD;       // [NHEADS][FLD]
    __shared__ float wsh[NHEADS * NHEADS];
    __shared__ float bsh[NHEADS];

    int tid = threadIdx.x;
    int lane = tid & 31;
    int warp = tid >> 5;                   // 0..11 = head
    int bb = blockIdx.x / SEQ;
    int n  = blockIdx.x % SEQ;

    if (tid < NHEADS * NHEADS) wsh[tid] = cw[tid];
    if (tid < NHEADS) bsh[tid] = cb[tid];

    const size_t hs = (size_t)SEQ * SEQ;
    size_t rowbase = ((size_t)bb * NHEADS * SEQ + n) * SEQ;   // (b, h=0, n, 0)

    // Phase 1: load raw logits, one warp per head (32 float4 per lane? 8 f4 each)
    {
        const float4* src = (const float4*)(g_qk + rowbase + (size_t)warp * hs);
        float4* dst4 = (float4*)(buf + warp * FLD);
#pragma unroll
        for (int i = 0; i < SEQ / 4 / 32; i++) {   // 8 iters
            dst4[lane + i * 32] = src[lane + i * 32];
        }
    }
    __syncthreads();

    // Phase 2: uncertainty. Threads stride over m.
    for (int m = tid; m < SEQ; m += 384) {
        float qv[NHEADS];
#pragma unroll
        for (int h = 0; h < NHEADS; h++) qv[h] = buf[h * FLD + m];
#pragma unroll
        for (int g = 0; g < NHEADS; g++) {
            float s = bsh[g];
#pragma unroll
            for (int h = 0; h < NHEADS; h++) s = fmaf(qv[h], wsh[g * NHEADS + h], s);
            float u = 1.0f / (1.0f + expf(-s));
            ubuf[g * FLD + m] = u;
            u_out[rowbase + (size_t)g * hs + m] = u;
        }
    }
    __syncthreads();

    // Phase 3: per-head softmax + attn. Warp h owns head h's 1024-row.
    {
        float* b_ = buf + warp * FLD;
        float* u_ = ubuf + warp * FLD;
        const float* r_ = r + rowbase + (size_t)warp * hs;
        float* am_ = am_out + rowbase + (size_t)warp * hs;
        float* at_ = g_qk + rowbase + (size_t)warp * hs;

        // max
        float mx = -1e30f;
#pragma unroll
        for (int i = 0; i < SEQ / 32; i++) mx = fmaxf(mx, b_[lane + i * 32]);
#pragma unroll
        for (int o = 16; o > 0; o >>= 1) mx = fmaxf(mx, __shfl_xor_sync(0xffffffffu, mx, o));

        // exp + sum
        float s = 0.f;
#pragma unroll
        for (int i = 0; i < SEQ / 32; i++) {
            int m = lane + i * 32;
            float e = expf((b_[m] - mx) * QK_SCALE);
            b_[m] = e;
            s += e;
        }
#pragma unroll
        for (int o = 16; o > 0; o >>= 1) s += __shfl_xor_sync(0xffffffffu, s, o);
        float inv = 1.0f / s;

        // write am + attn
#pragma unroll
        for (int i = 0; i < SEQ / 32; i++) {
            int m = lane + i * 32;
            float a = b_[m] * inv;
            am_[m] = a;
            at_[m] = fmaf(u_[m], r_[m], a);
        }
    }
}

// ---------------------------------------------------------------------------
// AV (tf32 mma): out[b,h,n,d] = sum_m attn[b,h,n,m] * v[b,h,m,d]
// BM=128(n), BN=64(d), BK=32. 8 warps 4x2, warp tile 32x32 (mt2 x nt4).
// ---------------------------------------------------------------------------
__global__ __launch_bounds__(256)
void av_tf32_kernel(float* __restrict__ outp) {
    constexpr int BM = 128, BK = 32;
    constexpr int LDV = 3 * DMODEL;
    __shared__ uint32_t As[BK][BM + 4];
    __shared__ uint32_t Vs[BK][72];

    int bh = blockIdx.z;
    int b = bh / NHEADS, h = bh % NHEADS;
    const float* attn = g_qk + (size_t)bh * SEQ * SEQ + (size_t)(blockIdx.y * BM) * SEQ;
    const float* v = g_qkv + (size_t)b * SEQ * LDV + 2 * DMODEL + h * HDIM;

    int tid = threadIdx.x;
    int lane = tid & 31;
    int warp = tid >> 5;
    int warpM = warp >> 1;        // 0..3  -> 32-row band
    int warpN = warp & 1;         // 0..1  -> 32-col band
    int qk_ = lane & 3;
    int qr = lane >> 2;

    float acc[2][4][4];
#pragma unroll
    for (int i = 0; i < 2; i++)
#pragma unroll
        for (int j = 0; j < 4; j++)
#pragma unroll
            for (int f = 0; f < 4; f++) acc[i][j][f] = 0.f;

    for (int k0 = 0; k0 < SEQ; k0 += BK) {
        // A tile: attn[n][m], 128 rows x 32 k
#pragma unroll
        for (int e = tid; e < 1024; e += 256) {
            int row = e >> 3, c4 = e & 7;
            float4 a = *(const float4*)(attn + (size_t)row * SEQ + k0 + c4 * 4);
            As[c4 * 4 + 0][row] = f2tf32(a.x); As[c4 * 4 + 1][row] = f2tf32(a.y);
            As[c4 * 4 + 2][row] = f2tf32(a.z); As[c4 * 4 + 3][row] = f2tf32(a.w);
        }
        // V tile: Vs[k][d], 32 rows x 64 cols
#pragma unroll
        for (int e = tid; e < 512; e += 256) {
            int row = e >> 4, c4 = e & 15;
            float4 vv = *(const float4*)(v + (size_t)(k0 + row) * LDV + c4 * 4);
            Vs[row][c4 * 4 + 0] = f2tf32(vv.x); Vs[row][c4 * 4 + 1] = f2tf32(vv.y);
            Vs[row][c4 * 4 + 2] = f2tf32(vv.z); Vs[row][c4 * 4 + 3] = f2tf32(vv.w);
        }
        __syncthreads();

#pragma unroll
        for (int kk = 0; kk < 4; kk++) {
            int kb = kk * 8;
            uint32_t afrag[2][4];
            uint32_t bfrag[4][2];
#pragma unroll
            for (int mt = 0; mt < 2; mt++) {
                int rb = warpM * 32 + mt * 16 + qr;
                afrag[mt][0] = As[kb + qk_][rb];
                afrag[mt][1] = As[kb + qk_][rb + 8];
                afrag[mt][2] = As[kb + qk_ + 4][rb];
                afrag[mt][3] = As[kb + qk_ + 4][rb + 8];
            }
#pragma unroll
            for (int nt = 0; nt < 4; nt++) {
                int cb = warpN * 32 + nt * 8 + qr;
                bfrag[nt][0] = Vs[kb + qk_][cb];
                bfrag[nt][1] = Vs[kb + qk_ + 4][cb];
            }
#pragma unroll
            for (int mt = 0; mt < 2; mt++)
#pragma unroll
                for (int nt = 0; nt < 4; nt++)
                    mma_tf32(acc[mt][nt], afrag[mt], bfrag[nt]);
        }
        __syncthreads();
    }

#pragma unroll
    for (int mt = 0; mt < 2; mt++) {
        int n0 = blockIdx.y * BM + warpM * 32 + mt * 16 + qr;
#pragma unroll
        for (int nt = 0; nt < 4; nt++) {
            int col = h * HDIM + warpN * 32 + nt * 8 + 2 * qk_;
            float* o0 = outp + (size_t)(b * SEQ + n0) * DMODEL + col;
            float* o1 = outp + (size_t)(b * SEQ + n0 + 8) * DMODEL + col;
            *(float2*)o0 = make_float2(acc[mt][nt][0], acc[mt][nt][1]);
            *(float2*)o1 = make_float2(acc[mt][nt][2], acc[mt][nt][3]);
        }
    }
}

// ---------------------------------------------------------------------------
// Launch
// ---------------------------------------------------------------------------
extern "C" void kernel_launch(void* const* d_in, const int* in_sizes, int n_in,
                              void* d_out, int out_size) {
    const float* x      = (const float*)d_in[0];
    const float* r      = (const float*)d_in[1];
    const float* ln1_g  = (const float*)d_in[2];
    const float* ln1_b  = (const float*)d_in[3];
    const float* qkv_w  = (const float*)d_in[4];
    const float* qkv_b  = (const float*)d_in[5];
    const float* conv_w = (const float*)d_in[6];
    const float* conv_b = (const float*)d_in[7];
    const float* proj_w = (const float*)d_in[8];
    const float* proj_b = (const float*)d_in[9];
    const float* ln2_g  = (const float*)d_in[10];
    const float* ln2_b  = (const float*)d_in[11];
    const float* fc1_w  = (const float*)d_in[12];
    const float* fc1_b  = (const float*)d_in[13];
    const float* fc2_w  = (const float*)d_in[14];
    const float* fc2_b  = (const float*)d_in[15];

    float* out    = (float*)d_out;
    float* out_x  = out;
    float* out_am = out + (size_t)TTOK * DMODEL;
    float* out_u  = out_am + (size_t)BDIM * NHEADS * SEQ * SEQ;

    static float *p_h = nullptr, *p_qkv = nullptr, *p_qk = nullptr,
                 *p_ao = nullptr, *p_x1 = nullptr, *p_mlp = nullptr;
    static bool attr_done = false;
    if (!p_h) {
        cudaGetSymbolAddress((void**)&p_h, g_h);
        cudaGetSymbolAddress((void**)&p_qkv, g_qkv);
        cudaGetSymbolAddress((void**)&p_qk, g_qk);
        cudaGetSymbolAddress((void**)&p_ao, g_attnout);
        cudaGetSymbolAddress((void**)&p_x1, g_x1);
        cudaGetSymbolAddress((void**)&p_mlp, g_mlp);
    }
    const int fused_smem = 2 * NHEADS * FLD * sizeof(float);   // ~98.7 KB
    if (!attr_done) {
        cudaFuncSetAttribute(fused_su_kernel, cudaFuncAttributeMaxDynamicSharedMemorySize, fused_smem);
        attr_done = true;
    }

    // 1. LN1
    ln_kernel<<<TTOK, 256>>>(x, ln1_g, ln1_b, p_h);

    // 2. QKV (tf32)
    gemm_tf32<0, false><<<dim3(3 * DMODEL / 128, TTOK / 128), 256>>>(
        p_h, qkv_w, qkv_b, nullptr, p_qkv, TTOK, 3 * DMODEL, DMODEL);

    // 3. QK^T raw logits (exact fp32)
    qk_kernel<<<dim3(SEQ / 128, SEQ / 128, BDIM * NHEADS), 256>>>();

    // 4. fused softmax + uncertainty + attn build (attn overwrites g_qk)
    fused_su_kernel<<<BDIM * SEQ, 384, fused_smem>>>(r, conv_w, conv_b, out_am, out_u);

    // 5. AV (tf32)
    av_tf32_kernel<<<dim3(1, SEQ / 128, BDIM * NHEADS), 256>>>(p_ao);

    // 6. proj + residual(x) (tf32)
    gemm_tf32<0, true><<<dim3(DMODEL / 128, TTOK / 128), 256>>>(
        p_ao, proj_w, proj_b, x, p_x1, TTOK, DMODEL, DMODEL);

    // 7. LN2
    ln_kernel<<<TTOK, 256>>>(p_x1, ln2_g, ln2_b, p_h);

    // 8. fc1 + gelu (tf32)
    gemm_tf32<1, false><<<dim3(DMLP / 128, TTOK / 128), 256>>>(
        p_h, fc1_w, fc1_b, nullptr, p_mlp, TTOK, DMLP, DMODEL);

    // 9. fc2 + residual(x1) (tf32)
    gemm_tf32<0, true><<<dim3(DMODEL / 128, TTOK / 128), 256>>>(
        p_mlp, fc2_w, fc2_b, p_x1, out_x, TTOK, DMODEL, DMLP);
}